// round 6
// baseline (speedup 1.0000x reference)
#include <cuda_runtime.h>

#define BATCH 4096
#define SEQ   200
#define EMB   128
#define GRID  2048          // single resident wave (13.8 CTAs/SM <= 16), 2 rows per CTA
#define ROWS_PER_CTA (BATCH / GRID)

__global__ __launch_bounds__(128)
void pool_linear_kernel(const int* __restrict__ x,
                        const float* __restrict__ emb,
                        const float* __restrict__ W,
                        const float* __restrict__ bias,
                        float* __restrict__ out)
{
    const int tid  = threadIdx.x;
    const int warp = tid >> 5;
    const int lane = tid & 31;

    __shared__ __align__(16) float sacc[4][EMB];
    __shared__ __align__(16) float red[2][EMB];
    __shared__ int   sidx[SEQ];     // compacted valid indices
    __shared__ int   scount;

    #pragma unroll
    for (int r = 0; r < ROWS_PER_CTA; r++) {
        const int row = blockIdx.x + r * GRID;

        if (tid == 0) scount = 0;
        __syncthreads();

        // Load + warp-ballot compaction of valid indices (order irrelevant for a sum).
        {
            const int* xr = x + row * SEQ;
            #pragma unroll
            for (int base = 0; base < SEQ; base += 128) {
                int s   = base + tid;
                int idx = (s < SEQ) ? xr[s] : -1;
                bool valid = (idx >= 0);
                unsigned m = __ballot_sync(0xFFFFFFFFu, valid);
                int nwarp  = __popc(m);
                int wbase;
                if (lane == 0) wbase = atomicAdd(&scount, nwarp);
                wbase = __shfl_sync(0xFFFFFFFFu, wbase, 0);
                if (valid) {
                    int off = __popc(m & ((1u << lane) - 1u));
                    sidx[wbase + off] = idx;
                }
            }
        }
        __syncthreads();

        const int nv = scount;           // >= 1 (column 0 always valid)

        float4 acc = make_float4(0.f, 0.f, 0.f, 0.f);

        // Unconditional gathers over exactly the valid tokens; warp w takes i = w, w+4, ...
        #pragma unroll 8
        for (int i = warp; i < nv; i += 4) {
            int idx = sidx[i];           // smem broadcast
            const float4* e = reinterpret_cast<const float4*>(emb + idx * EMB);
            float4 v = __ldg(&e[lane]);  // coalesced 512B row load
            acc.x += v.x; acc.y += v.y; acc.z += v.z; acc.w += v.w;
        }

        // Cross-warp reduction of the 128-dim accumulator.
        reinterpret_cast<float4*>(sacc[warp])[lane] = acc;
        __syncthreads();

        const int d = tid;               // dim owned by this thread
        float total  = sacc[0][d] + sacc[1][d] + sacc[2][d] + sacc[3][d];
        float pooled = total * (1.0f / (float)nv);

        // Tiny linear: out[row][k] = sum_d pooled[d]*W[k][d] + b[k]
        red[0][d] = pooled * W[d];
        red[1][d] = pooled * W[EMB + d];
        __syncthreads();

        if (warp < 2) {
            float v = red[warp][lane] + red[warp][lane + 32]
                    + red[warp][lane + 64] + red[warp][lane + 96];
            #pragma unroll
            for (int off = 16; off > 0; off >>= 1)
                v += __shfl_down_sync(0xFFFFFFFFu, v, off);
            if (lane == 0)
                out[row * 2 + warp] = v + bias[warp];
        }
        __syncthreads();                 // protect smem reuse for next row
    }
}

extern "C" void kernel_launch(void* const* d_in, const int* in_sizes, int n_in,
                              void* d_out, int out_size)
{
    const int* x     = (const int*)d_in[0];       // int32 [4096,200]
    const float* emb = (const float*)d_in[1];     // [100000,128]
    const float* W   = (const float*)d_in[2];     // [2,128]
    const float* b   = (const float*)d_in[3];     // [2]
    float* out       = (float*)d_out;             // [4096,2]

    pool_linear_kernel<<<GRID, 128>>>(x, emb, W, b, out);
}